// round 2
// baseline (speedup 1.0000x reference)
#include <cuda_runtime.h>
#include <cstdint>

// Problem constants (fixed by the reference)
#define N_NODES 100000
#define N_EDGES 1600000
#define D       128
#define N_REL   48
#define HALF_REL 24
#define BN_EPS  1e-5f

// Scratch (device globals: allocation-free per harness rules)
__device__ float g_feats[N_NODES * D];   // 51.2 MB: x @ W
__device__ float g_sum[D];
__device__ float g_sumsq[D];

// ---------------------------------------------------------------------------
// K0: zero the aggregation buffer (d_out, used in place) and the BN partials
// ---------------------------------------------------------------------------
__global__ void zero_kernel(float4* __restrict__ out4) {
    size_t i = (size_t)blockIdx.x * blockDim.x + threadIdx.x;
    size_t n4 = (size_t)N_NODES * D / 4;
    size_t stride = (size_t)gridDim.x * blockDim.x;
    for (; i < n4; i += stride)
        out4[i] = make_float4(0.f, 0.f, 0.f, 0.f);
    size_t g = (size_t)blockIdx.x * blockDim.x + threadIdx.x;
    if (g < D) { g_sum[g] = 0.f; g_sumsq[g] = 0.f; }
}

// ---------------------------------------------------------------------------
// K1: feats = x @ W   (fp32, smem-staged x rows, W streamed via L1)
// 16 rows per block, 128 threads; thread j owns output column j.
// ---------------------------------------------------------------------------
#define GEMM_ROWS 16
__global__ __launch_bounds__(128) void gemm_kernel(
    const float* __restrict__ x, const float* __restrict__ w) {
    __shared__ float4 xs[GEMM_ROWS][D / 4];   // 8 KB

    const int tid = threadIdx.x;              // 0..127
    const int row0 = blockIdx.x * GEMM_ROWS;

    // Load 16 x-rows (coalesced float4)
    const float4* xv = (const float4*)(x + (size_t)row0 * D);
    #pragma unroll
    for (int i = 0; i < GEMM_ROWS * (D / 4) / 128; i++) {
        int idx = tid + i * 128;
        xs[idx / (D / 4)][idx % (D / 4)] = xv[idx];
    }
    __syncthreads();

    const int j = tid;                         // output column
    float acc[GEMM_ROWS];
    #pragma unroll
    for (int r = 0; r < GEMM_ROWS; r++) acc[r] = 0.f;

    #pragma unroll 4
    for (int kk = 0; kk < D / 4; kk++) {
        // W rows 4kk..4kk+3, column j (coalesced across threads, L1-resident)
        float w0 = __ldg(w + (4 * kk + 0) * D + j);
        float w1 = __ldg(w + (4 * kk + 1) * D + j);
        float w2 = __ldg(w + (4 * kk + 2) * D + j);
        float w3 = __ldg(w + (4 * kk + 3) * D + j);
        #pragma unroll
        for (int r = 0; r < GEMM_ROWS; r++) {
            float4 xr = xs[r][kk];             // warp-broadcast LDS.128
            acc[r] += xr.x * w0;
            acc[r] += xr.y * w1;
            acc[r] += xr.z * w2;
            acc[r] += xr.w * w3;
        }
    }

    #pragma unroll
    for (int r = 0; r < GEMM_ROWS; r++)
        g_feats[(size_t)(row0 + r) * D + j] = acc[r];
}

// ---------------------------------------------------------------------------
// K2: per-edge gather * alpha-pair, scatter-add into d_out (vector RED)
// One warp per edge: lane l handles columns [4l, 4l+4).
// Edge metadata loaded once per warp (lanes 0-2) and shfl-broadcast.
// ---------------------------------------------------------------------------
__global__ __launch_bounds__(256) void scatter_kernel(
    const int* __restrict__ src, const int* __restrict__ dst,
    const int* __restrict__ etype, const float* __restrict__ alpha,
    float* __restrict__ out) {
    const int warp = (blockIdx.x * (blockDim.x >> 5)) + (threadIdx.x >> 5);
    if (warp >= N_EDGES) return;
    const int lane = threadIdx.x & 31;

    // lanes 0,1,2 fetch s, d, t respectively; broadcast to the warp
    int meta = 0;
    if (lane == 0)      meta = __ldg(src + warp);
    else if (lane == 1) meta = __ldg(dst + warp);
    else if (lane == 2) meta = __ldg(etype + warp);
    const int s = __shfl_sync(0xffffffffu, meta, 0);
    const int d = __shfl_sync(0xffffffffu, meta, 1);
    const int t = __shfl_sync(0xffffffffu, meta, 2);

    const int tt = (t >= HALF_REL) ? (t - HALF_REL) : (t + HALF_REL);
    const float a = __ldg(alpha + t) + __ldg(alpha + tt);   // L1-resident (48 floats)

    const float4 v = *((const float4*)(g_feats + (size_t)s * D) + lane);
    float* op = out + (size_t)d * D + lane * 4;

    // Vector reduction to global (sm_90+): one 16B atomic-add, no return.
    asm volatile(
        "red.global.add.v4.f32 [%0], {%1, %2, %3, %4};"
        :: "l"(op), "f"(v.x * a), "f"(v.y * a), "f"(v.z * a), "f"(v.w * a)
        : "memory");
}

// ---------------------------------------------------------------------------
// K3: per-column sum / sumsq (BN statistics), float4-vectorized
// blockDim=128: thread tid handles column group (tid%32)*4, rows strided by 4.
// ---------------------------------------------------------------------------
__global__ __launch_bounds__(128) void bn_reduce_kernel(const float* __restrict__ out) {
    const int cg   = threadIdx.x & 31;         // column group 0..31 -> cols 4cg..4cg+3
    const int rsub = threadIdx.x >> 5;         // 0..3 row sub-stride
    float4 s  = make_float4(0.f, 0.f, 0.f, 0.f);
    float4 s2 = make_float4(0.f, 0.f, 0.f, 0.f);
    for (int row = blockIdx.x * 4 + rsub; row < N_NODES; row += gridDim.x * 4) {
        float4 v = *((const float4*)(out + (size_t)row * D) + cg);
        s.x += v.x;  s.y += v.y;  s.z += v.z;  s.w += v.w;
        s2.x += v.x * v.x;  s2.y += v.y * v.y;  s2.z += v.z * v.z;  s2.w += v.w * v.w;
    }
    atomicAdd(&g_sum[cg * 4 + 0], s.x);
    atomicAdd(&g_sum[cg * 4 + 1], s.y);
    atomicAdd(&g_sum[cg * 4 + 2], s.z);
    atomicAdd(&g_sum[cg * 4 + 3], s.w);
    atomicAdd(&g_sumsq[cg * 4 + 0], s2.x);
    atomicAdd(&g_sumsq[cg * 4 + 1], s2.y);
    atomicAdd(&g_sumsq[cg * 4 + 2], s2.w * 0.f + s2.z);
    atomicAdd(&g_sumsq[cg * 4 + 3], s2.w);
}

// ---------------------------------------------------------------------------
// K4: normalize in place: (x-mean)*rsqrt(var+eps)*gamma + beta
// ---------------------------------------------------------------------------
__global__ __launch_bounds__(256) void bn_finalize_kernel(
    float4* __restrict__ out4,
    const float* __restrict__ gamma,
    const float* __restrict__ beta) {
    const float invN = 1.0f / (float)N_NODES;
    size_t i = (size_t)blockIdx.x * blockDim.x + threadIdx.x;
    size_t n4 = (size_t)N_NODES * D / 4;
    size_t stride = (size_t)gridDim.x * blockDim.x;
    for (; i < n4; i += stride) {
        int j = (int)((i & (D / 4 - 1)) * 4);
        float4 v = out4[i];
        #pragma unroll
        for (int c = 0; c < 4; c++) {
            float* vc = (&v.x) + c;
            float mean = g_sum[j + c] * invN;
            float var  = g_sumsq[j + c] * invN - mean * mean;
            float scale = rsqrtf(var + BN_EPS) * __ldg(gamma + j + c);
            *vc = (*vc - mean) * scale + __ldg(beta + j + c);
        }
        out4[i] = v;
    }
}

// ---------------------------------------------------------------------------
// Launch
// inputs (metadata order): x, weight, alpha, gamma, beta, src, dst, edge_type
// output: [N_NODES, D] float32
// ---------------------------------------------------------------------------
extern "C" void kernel_launch(void* const* d_in, const int* in_sizes, int n_in,
                              void* d_out, int out_size) {
    const float* x      = (const float*)d_in[0];
    const float* weight = (const float*)d_in[1];
    const float* alpha  = (const float*)d_in[2];
    const float* gamma  = (const float*)d_in[3];
    const float* beta   = (const float*)d_in[4];
    const int*   src    = (const int*)d_in[5];
    const int*   dst    = (const int*)d_in[6];
    const int*   etype  = (const int*)d_in[7];
    float* out = (float*)d_out;

    // K0: zero agg buffer + BN partials
    zero_kernel<<<12500, 256>>>((float4*)out);

    // K1: feats = x @ W
    gemm_kernel<<<N_NODES / GEMM_ROWS, 128>>>(x, weight);

    // K2: edge scatter (8 edges per 256-thread block)
    scatter_kernel<<<N_EDGES / 8, 256>>>(src, dst, etype, alpha, out);

    // K3: BN stats
    bn_reduce_kernel<<<1184, 128>>>(out);

    // K4: normalize
    bn_finalize_kernel<<<2048, 256>>>((float4*)out, gamma, beta);
}

// round 6
// speedup vs baseline: 1.7395x; 1.7395x over previous
#include <cuda_runtime.h>
#include <cstdint>

// Problem constants (fixed by the reference)
#define N_NODES 100000
#define N_EDGES 1600000
#define D       128
#define N_REL   48
#define HALF_REL 24
#define BN_EPS  1e-5f

// Scratch (device globals: allocation-free per harness rules)
__device__ float g_feats[N_NODES * D];   // 51.2 MB: x @ W
__device__ float g_sum[D];
__device__ float g_sumsq[D];
__device__ float g_alpha_pair[N_REL];    // alpha[t] + alpha[t_trans]

// ---------------------------------------------------------------------------
// K0: zero the aggregation buffer (d_out, used in place), BN partials,
// and precompute the 48-entry alpha-pair table.
// ---------------------------------------------------------------------------
__global__ void zero_kernel(float4* __restrict__ out4,
                            const float* __restrict__ alpha) {
    size_t i = (size_t)blockIdx.x * blockDim.x + threadIdx.x;
    size_t n4 = (size_t)N_NODES * D / 4;
    size_t stride = (size_t)gridDim.x * blockDim.x;
    for (; i < n4; i += stride)
        out4[i] = make_float4(0.f, 0.f, 0.f, 0.f);
    size_t g = (size_t)blockIdx.x * blockDim.x + threadIdx.x;
    if (g < D) { g_sum[g] = 0.f; g_sumsq[g] = 0.f; }
    if (blockIdx.x == 0 && threadIdx.x < N_REL) {
        int t = threadIdx.x;
        int tt = (t >= HALF_REL) ? (t - HALF_REL) : (t + HALF_REL);
        g_alpha_pair[t] = alpha[t] + alpha[tt];
    }
}

// ---------------------------------------------------------------------------
// K1: feats = x @ W   (fp32, smem-staged x rows, W streamed via L1)
// 16 rows per block, 128 threads; thread j owns output column j.
// ---------------------------------------------------------------------------
#define GEMM_ROWS 16
__global__ __launch_bounds__(128) void gemm_kernel(
    const float* __restrict__ x, const float* __restrict__ w) {
    __shared__ float4 xs[GEMM_ROWS][D / 4];   // 8 KB

    const int tid = threadIdx.x;              // 0..127
    const int row0 = blockIdx.x * GEMM_ROWS;

    const float4* xv = (const float4*)(x + (size_t)row0 * D);
    #pragma unroll
    for (int i = 0; i < GEMM_ROWS * (D / 4) / 128; i++) {
        int idx = tid + i * 128;
        xs[idx / (D / 4)][idx % (D / 4)] = xv[idx];
    }
    __syncthreads();

    const int j = tid;                         // output column
    float acc[GEMM_ROWS];
    #pragma unroll
    for (int r = 0; r < GEMM_ROWS; r++) acc[r] = 0.f;

    #pragma unroll 4
    for (int kk = 0; kk < D / 4; kk++) {
        float w0 = __ldg(w + (4 * kk + 0) * D + j);
        float w1 = __ldg(w + (4 * kk + 1) * D + j);
        float w2 = __ldg(w + (4 * kk + 2) * D + j);
        float w3 = __ldg(w + (4 * kk + 3) * D + j);
        #pragma unroll
        for (int r = 0; r < GEMM_ROWS; r++) {
            float4 xr = xs[r][kk];
            acc[r] += xr.x * w0;
            acc[r] += xr.y * w1;
            acc[r] += xr.z * w2;
            acc[r] += xr.w * w3;
        }
    }

    #pragma unroll
    for (int r = 0; r < GEMM_ROWS; r++)
        g_feats[(size_t)(row0 + r) * D + j] = acc[r];
}

// ---------------------------------------------------------------------------
// K2: edge scatter, 4 edges per warp.
// Quarter q = lane>>3 owns edge 4*warp+q; lane c = lane&7 covers float4
// column indices {c, c+8, c+16, c+24} of that edge's 128-col row.
// -> 4 independent LDG.128 + 4 independent RED.128 per lane (MLP=4).
// Meta (src,dst,etype for 4 edges) loaded by lanes 0-11, shfl-broadcast.
// ---------------------------------------------------------------------------
__global__ __launch_bounds__(256) void scatter_kernel(
    const int* __restrict__ src, const int* __restrict__ dst,
    const int* __restrict__ etype, float* __restrict__ out) {
    const int warp = (blockIdx.x * (blockDim.x >> 5)) + (threadIdx.x >> 5);
    const int e0 = warp * 4;
    if (e0 >= N_EDGES) return;
    const int lane = threadIdx.x & 31;
    const int q = lane >> 3;          // 0..3: which edge in the group
    const int c = lane & 7;           // 0..7: column sub-slice

    // lanes 0-3: src[e0+l]; lanes 4-7: dst[e0+l-4]; lanes 8-11: etype[e0+l-8]
    int meta = 0;
    if (lane < 4)        meta = __ldg(src + e0 + lane);
    else if (lane < 8)   meta = __ldg(dst + e0 + lane - 4);
    else if (lane < 12)  meta = __ldg(etype + e0 + lane - 8);
    const int s = __shfl_sync(0xffffffffu, meta, q);
    const int d = __shfl_sync(0xffffffffu, meta, 4 + q);
    const int t = __shfl_sync(0xffffffffu, meta, 8 + q);

    const float a = g_alpha_pair[t];  // L1-resident, 48 floats

    const float4* fp = (const float4*)(g_feats + (size_t)s * D);
    float4 v0 = fp[c];
    float4 v1 = fp[c + 8];
    float4 v2 = fp[c + 16];
    float4 v3 = fp[c + 24];

    float* ob = out + (size_t)d * D;
    #define RED4(ptr, v)                                              \
        asm volatile("red.global.add.v4.f32 [%0], {%1, %2, %3, %4};"  \
            :: "l"(ptr), "f"((v).x * a), "f"((v).y * a),              \
               "f"((v).z * a), "f"((v).w * a) : "memory")
    RED4(ob + (c) * 4, v0);
    RED4(ob + (c + 8) * 4, v1);
    RED4(ob + (c + 16) * 4, v2);
    RED4(ob + (c + 24) * 4, v3);
    #undef RED4
}

// ---------------------------------------------------------------------------
// K3: per-column sum / sumsq (BN statistics).
// 256 threads: cg = tid&31 -> columns [4cg,4cg+4); rsub = tid>>5 in 0..7.
// Manual 4x unroll -> 4 independent LDG.128 in flight per thread (MLP=4).
// Smem tree-reduction across rsub, then 256 atomics per block (not 1024).
// ---------------------------------------------------------------------------
#define BNR_GRID 1184   // 8 blocks/SM * 148 SMs
__global__ __launch_bounds__(256) void bn_reduce_kernel(const float* __restrict__ out) {
    const int cg   = threadIdx.x & 31;
    const int rsub = threadIdx.x >> 5;          // 0..7
    const int rstride = BNR_GRID * 8;           // 9472 rows

    float4 s  = make_float4(0.f, 0.f, 0.f, 0.f);
    float4 s2 = make_float4(0.f, 0.f, 0.f, 0.f);

    int row = blockIdx.x * 8 + rsub;
    for (; row + 3 * rstride < N_NODES; row += 4 * rstride) {
        float4 v0 = *((const float4*)(out + (size_t)(row               ) * D) + cg);
        float4 v1 = *((const float4*)(out + (size_t)(row +     rstride) * D) + cg);
        float4 v2 = *((const float4*)(out + (size_t)(row + 2 * rstride) * D) + cg);
        float4 v3 = *((const float4*)(out + (size_t)(row + 3 * rstride) * D) + cg);
        s.x += v0.x + v1.x + v2.x + v3.x;
        s.y += v0.y + v1.y + v2.y + v3.y;
        s.z += v0.z + v1.z + v2.z + v3.z;
        s.w += v0.w + v1.w + v2.w + v3.w;
        s2.x += v0.x * v0.x + v1.x * v1.x + v2.x * v2.x + v3.x * v3.x;
        s2.y += v0.y * v0.y + v1.y * v1.y + v2.y * v2.y + v3.y * v3.y;
        s2.z += v0.z * v0.z + v1.z * v1.z + v2.z * v2.z + v3.z * v3.z;
        s2.w += v0.w * v0.w + v1.w * v1.w + v2.w * v2.w + v3.w * v3.w;
    }
    for (; row < N_NODES; row += rstride) {
        float4 v = *((const float4*)(out + (size_t)row * D) + cg);
        s.x += v.x;  s.y += v.y;  s.z += v.z;  s.w += v.w;
        s2.x += v.x * v.x;  s2.y += v.y * v.y;  s2.z += v.z * v.z;  s2.w += v.w * v.w;
    }

    __shared__ float4 sh_s[8][32];
    __shared__ float4 sh_s2[8][32];
    sh_s[rsub][cg] = s;
    sh_s2[rsub][cg] = s2;
    __syncthreads();
    #pragma unroll
    for (int off = 4; off >= 1; off >>= 1) {
        if (rsub < off) {
            float4 a = sh_s[rsub][cg],  b = sh_s[rsub + off][cg];
            float4 c = sh_s2[rsub][cg], e = sh_s2[rsub + off][cg];
            a.x += b.x; a.y += b.y; a.z += b.z; a.w += b.w;
            c.x += e.x; c.y += e.y; c.z += e.z; c.w += e.w;
            sh_s[rsub][cg] = a;
            sh_s2[rsub][cg] = c;
        }
        __syncthreads();
    }
    if (rsub == 0) {
        float4 fs  = sh_s[0][cg];
        float4 fs2 = sh_s2[0][cg];
        atomicAdd(&g_sum[cg * 4 + 0], fs.x);
        atomicAdd(&g_sum[cg * 4 + 1], fs.y);
        atomicAdd(&g_sum[cg * 4 + 2], fs.z);
        atomicAdd(&g_sum[cg * 4 + 3], fs.w);
        atomicAdd(&g_sumsq[cg * 4 + 0], fs2.x);
        atomicAdd(&g_sumsq[cg * 4 + 1], fs2.y);
        atomicAdd(&g_sumsq[cg * 4 + 2], fs2.z);
        atomicAdd(&g_sumsq[cg * 4 + 3], fs2.w);
    }
}

// ---------------------------------------------------------------------------
// K4: normalize in place. Per-column scale/shift precomputed into smem once
// per block, then pure streaming read+write.
// ---------------------------------------------------------------------------
__global__ __launch_bounds__(256) void bn_finalize_kernel(
    float4* __restrict__ out4,
    const float* __restrict__ gamma,
    const float* __restrict__ beta) {
    __shared__ float sh_scale[D];
    __shared__ float sh_shift[D];
    const float invN = 1.0f / (float)N_NODES;
    if (threadIdx.x < D) {
        int j = threadIdx.x;
        float mean = g_sum[j] * invN;
        float var  = g_sumsq[j] * invN - mean * mean;
        float sc   = rsqrtf(var + BN_EPS) * __ldg(gamma + j);
        sh_scale[j] = sc;
        sh_shift[j] = __ldg(beta + j) - mean * sc;
    }
    __syncthreads();

    size_t i = (size_t)blockIdx.x * blockDim.x + threadIdx.x;
    size_t n4 = (size_t)N_NODES * D / 4;
    size_t stride = (size_t)gridDim.x * blockDim.x;
    for (; i < n4; i += stride) {
        int j = (int)((i & (D / 4 - 1)) * 4);
        float4 v = out4[i];
        v.x = v.x * sh_scale[j + 0] + sh_shift[j + 0];
        v.y = v.y * sh_scale[j + 1] + sh_shift[j + 1];
        v.z = v.z * sh_scale[j + 2] + sh_shift[j + 2];
        v.w = v.w * sh_scale[j + 3] + sh_shift[j + 3];
        out4[i] = v;
    }
}

// ---------------------------------------------------------------------------
// Launch
// inputs (metadata order): x, weight, alpha, gamma, beta, src, dst, edge_type
// output: [N_NODES, D] float32
// ---------------------------------------------------------------------------
extern "C" void kernel_launch(void* const* d_in, const int* in_sizes, int n_in,
                              void* d_out, int out_size) {
    const float* x      = (const float*)d_in[0];
    const float* weight = (const float*)d_in[1];
    const float* alpha  = (const float*)d_in[2];
    const float* gamma  = (const float*)d_in[3];
    const float* beta   = (const float*)d_in[4];
    const int*   src    = (const int*)d_in[5];
    const int*   dst    = (const int*)d_in[6];
    const int*   etype  = (const int*)d_in[7];
    float* out = (float*)d_out;

    zero_kernel<<<12500, 256>>>((float4*)out, alpha);
    gemm_kernel<<<N_NODES / GEMM_ROWS, 128>>>(x, weight);
    // 4 edges/warp, 8 warps/block -> 32 edges/block
    scatter_kernel<<<N_EDGES / 32, 256>>>(src, dst, etype, out);
    bn_reduce_kernel<<<BNR_GRID, 256>>>(out);
    bn_finalize_kernel<<<2048, 256>>>((float4*)out, gamma, beta);
}